// round 11
// baseline (speedup 1.0000x reference)
#include <cuda_runtime.h>
#include <cstdint>

// LSTM: B=64, T=4096, H=128, gates i,f,g,o; Linear(H->1) on h_T.
// 64 clusters x 2 CTAs (128 CTAs, 1/SM). Each CTA owns hidden [rank*64, rank*64+64).
// Thread map: q = tid&3 (gate), jloc = tid>>2. 256 gate rows/CTA, weights fully
// register-resident as f32x2 pairs split into local/remote column halves.
// R3 skeleton with the exchange swapped to the DIRECT DSMEM path:
// senders do st.relaxed.shared::cluster (generic proxy, ~215cyc flight) followed
// by mbarrier.arrive.release.cluster on the peer's mbar (count=64);
// receivers try_wait with acquire.cluster. No async proxy, no expect_tx.
// Local-half dot overlaps the flight; MUFU.TANH; one __syncthreads per step.

#define B_ 64
#define T_ 4096
#define H_ 128
#define NT 256

__device__ __forceinline__ uint32_t smem_u32(const void* p) {
    uint32_t a;
    asm("{ .reg .u64 t; cvta.to.shared.u64 t, %1; cvt.u32.u64 %0, t; }" : "=r"(a) : "l"(p));
    return a;
}
__device__ __forceinline__ uint32_t ctarank() {
    uint32_t r; asm("mov.u32 %0, %%cluster_ctarank;" : "=r"(r)); return r;
}
__device__ __forceinline__ uint32_t mapa_u32(uint32_t a, uint32_t rk) {
    uint32_t r; asm("mapa.shared::cluster.u32 %0, %1, %2;" : "=r"(r) : "r"(a), "r"(rk)); return r;
}
__device__ __forceinline__ float tanh_fast(float x) {
    float y; asm("tanh.approx.f32 %0, %1;" : "=f"(y) : "f"(x)); return y;
}

// 32 packed FMAs (64 floats) of one column-half: W[32] f32x2 pairs vs 16 LDS.128 of h.
#define DOT_HALF(Wp, HP)                                                              \
    _Pragma("unroll")                                                                 \
    for (int i_ = 0; i_ < 8; i_++) {                                                  \
        ulonglong2 h2_ = (HP)[2*i_], h3_ = (HP)[2*i_ + 1];                            \
        asm("fma.rn.f32x2 %0, %1, %2, %0;" : "+l"(a0) : "l"((Wp)[4*i_    ]), "l"(h2_.x)); \
        asm("fma.rn.f32x2 %0, %1, %2, %0;" : "+l"(a1) : "l"((Wp)[4*i_ + 1]), "l"(h2_.y)); \
        asm("fma.rn.f32x2 %0, %1, %2, %0;" : "+l"(a2) : "l"((Wp)[4*i_ + 2]), "l"(h3_.x)); \
        asm("fma.rn.f32x2 %0, %1, %2, %0;" : "+l"(a3) : "l"((Wp)[4*i_ + 3]), "l"(h3_.y)); \
    }

// cluster-scope acquire: pairs with the senders' arrive.release.cluster, making
// their generic-proxy remote stores visible to this CTA.
#define MBAR_WAIT(addr, par)                                                          \
    asm volatile(                                                                     \
        "{\n\t"                                                                       \
        ".reg .pred P1;\n\t"                                                          \
        "WL_%=:\n\t"                                                                  \
        "mbarrier.try_wait.parity.acquire.cluster.shared::cta.b64 P1, [%0], %1, 0x989680;\n\t" \
        "@P1 bra.uni WD_%=;\n\t"                                                      \
        "bra.uni WL_%=;\n\t"                                                          \
        "WD_%=:\n\t"                                                                  \
        "}" :: "r"(addr), "r"(par) : "memory")

__global__ void __launch_bounds__(NT, 1) __cluster_dims__(2, 1, 1)
lstm_kernel(const float* __restrict__ data, const float* __restrict__ h0,
            const float* __restrict__ c0,   const float* __restrict__ W_ih,
            const float* __restrict__ W_hh, const float* __restrict__ b_ih,
            const float* __restrict__ b_hh, const float* __restrict__ W_out,
            const float* __restrict__ b_out, float* __restrict__ out)
{
    __shared__ __align__(16) float hbuf[2][H_];   // double-buffered full hidden state
    __shared__ __align__(16) float xs[T_];        // whole input sequence for this batch
    __shared__ __align__(8) unsigned long long mbar;

    const int tid   = threadIdx.x;
    const int q     = tid & 3;            // gate: 0=i,1=f,2=g,3=o
    const int jloc  = tid >> 2;           // 0..63
    const uint32_t rank = ctarank();
    const int batch = blockIdx.x >> 1;
    const int jglob = (int)rank * 64 + jloc;
    const int grow  = q * H_ + jglob;     // gate row in [0,512)

    // ---- register-resident weights, split by column half ----
    unsigned long long wl[32], wr[32];
    {
        const float* row = W_hh + (size_t)grow * H_;
        const ulonglong2* pl = reinterpret_cast<const ulonglong2*>(row + (int)rank * 64);
        const ulonglong2* pr = reinterpret_cast<const ulonglong2*>(row + (int)(rank ^ 1u) * 64);
        #pragma unroll
        for (int i = 0; i < 16; i++) { ulonglong2 v = pl[i]; wl[2*i] = v.x; wl[2*i+1] = v.y; }
        #pragma unroll
        for (int i = 0; i < 16; i++) { ulonglong2 v = pr[i]; wr[2*i] = v.x; wr[2*i+1] = v.y; }
    }
    const float wih  = W_ih[grow];
    const float bias = b_ih[grow] + b_hh[grow];
    // sigmoid(x) = 0.5*tanh(0.5x)+0.5 ; tanh for gate g (q==2)
    const float sA = (q == 2) ? 1.f : 0.5f;
    const float sB = (q == 2) ? 1.f : 0.5f;
    const float sC = (q == 2) ? 0.f : 0.5f;

    float c = c0[batch * H_ + jglob];     // replicated across 4 lanes of a unit

    if (tid < H_) hbuf[0][tid] = h0[batch * H_ + tid];
    for (int i = tid; i < T_; i += NT) xs[i] = data[(size_t)batch * T_ + i];

    const uint32_t mbar_a  = smem_u32(&mbar);
    const uint32_t hb_a    = smem_u32(&hbuf[0][0]);
    const uint32_t peer    = rank ^ 1u;
    const uint32_t peer_hb = mapa_u32(hb_a, peer);
    const uint32_t peer_mb = mapa_u32(mbar_a, peer);

    if (tid == 0) {
        asm volatile("mbarrier.init.shared.b64 [%0], %1;" :: "r"(mbar_a), "r"(64u) : "memory");
    }
    __syncthreads();
    // complete phase 0 trivially with 64 local arrives (q==0 threads)
    if (q == 0) {
        asm volatile("mbarrier.arrive.shared.b64 _, [%0];" :: "r"(mbar_a) : "memory");
    }
    // peer's mbarrier must be live before any remote arrive
    asm volatile("barrier.cluster.arrive.aligned;" ::: "memory");
    asm volatile("barrier.cluster.wait.aligned;"   ::: "memory");

    const int locOff = (int)rank * 64;
    const int remOff = (int)peer * 64;
    const int lane   = tid & 31;
    const int b4     = lane & ~3;
    const uint32_t send_base = peer_hb + (uint32_t)jglob * 4u;   // + w2*H_*4 per step

    // prologue: local-half partial dot over hbuf[0]
    unsigned long long a0 = 0ull, a1 = 0ull, a2 = 0ull, a3 = 0ull;
    {
        const ulonglong2* hp = reinterpret_cast<const ulonglong2*>(&hbuf[0][locOff]);
        DOT_HALF(wl, hp)
    }

    #pragma unroll 1
    for (int t = 0; t < T_; ++t) {
        const int p  = t & 1;
        const int w2 = p ^ 1;
        const float bx = fmaf(wih, xs[t], bias);   // before the wait

        // phase t: remote half of hbuf[p] has arrived (64 release-arrives)
        MBAR_WAIT(mbar_a, (uint32_t)p);

        // finish the dot with the remote half
        {
            const ulonglong2* hp = reinterpret_cast<const ulonglong2*>(&hbuf[p][remOff]);
            DOT_HALF(wr, hp)
        }
        float s;
        {
            unsigned long long s01, s23, st;
            asm("add.rn.f32x2 %0, %1, %2;" : "=l"(s01) : "l"(a0),  "l"(a1));
            asm("add.rn.f32x2 %0, %1, %2;" : "=l"(s23) : "l"(a2),  "l"(a3));
            asm("add.rn.f32x2 %0, %1, %2;" : "=l"(st)  : "l"(s01), "l"(s23));
            float lo, hi;
            asm("mov.b64 {%0,%1}, %2;" : "=f"(lo), "=f"(hi) : "l"(st));
            s = lo + hi;
        }

        const float pre = s + bx;
        const float act = fmaf(tanh_fast(pre * sA), sB, sC);

        // gather the 4 gates of this hidden unit (adjacent lanes)
        float gi = __shfl_sync(0xffffffffu, act, b4);
        float gf = __shfl_sync(0xffffffffu, act, b4 | 1);
        float gg = __shfl_sync(0xffffffffu, act, b4 | 2);
        float go = __shfl_sync(0xffffffffu, act, b4 | 3);

        c = fmaf(gf, c, gi * gg);
        const float hn = go * tanh_fast(c);

        if (q == 0) {
            hbuf[w2][jglob] = hn;                  // local copy
            // direct DSMEM store of the peer's copy, then release-arrive on the
            // peer's mbarrier (orders the store before the peer's acquire-wait)
            asm volatile("st.relaxed.cluster.shared::cluster.b32 [%0], %1;"
                         :: "r"(send_base + (uint32_t)(w2 * H_) * 4u),
                            "r"(__float_as_uint(hn)) : "memory");
            asm volatile("mbarrier.arrive.release.cluster.shared::cluster.b64 _, [%0];"
                         :: "r"(peer_mb) : "memory");
        }
        __syncthreads();   // local half of hbuf[w2] visible CTA-wide

        // local-half partial dot for the NEXT step (overlaps the DSMEM flight)
        a0 = a1 = a2 = a3 = 0ull;
        {
            const ulonglong2* hp = reinterpret_cast<const ulonglong2*>(&hbuf[w2][locOff]);
            DOT_HALF(wl, hp)
        }
    }

    // phase T_ (parity 0): remote half of hbuf[0] (final h) has arrived
    MBAR_WAIT(mbar_a, 0u);

    if (rank == 0 && tid < 32) {
        float s = 0.f;
        #pragma unroll
        for (int m = 0; m < 4; m++)
            s = fmaf(hbuf[0][tid * 4 + m], W_out[tid * 4 + m], s);
        #pragma unroll
        for (int off = 16; off; off >>= 1)
            s += __shfl_xor_sync(0xffffffffu, s, off);
        if (tid == 0) out[batch] = s + b_out[0];
    }

    // no CTA exits while its peer may still write this CTA's smem
    asm volatile("barrier.cluster.arrive.aligned;" ::: "memory");
    asm volatile("barrier.cluster.wait.aligned;"   ::: "memory");
}

extern "C" void kernel_launch(void* const* d_in, const int* in_sizes, int n_in,
                              void* d_out, int out_size)
{
    const float* data  = (const float*)d_in[0];
    const float* h0    = (const float*)d_in[1];
    const float* c0    = (const float*)d_in[2];
    const float* W_ih  = (const float*)d_in[3];
    const float* W_hh  = (const float*)d_in[4];
    const float* b_ih  = (const float*)d_in[5];
    const float* b_hh  = (const float*)d_in[6];
    const float* W_out = (const float*)d_in[7];
    const float* b_out = (const float*)d_in[8];
    float* out = (float*)d_out;

    lstm_kernel<<<B_ * 2, NT>>>(data, h0, c0, W_ih, W_hh, b_ih, b_hh, W_out, b_out, out);
}

// round 16
// speedup vs baseline: 1.6373x; 1.6373x over previous
#include <cuda_runtime.h>
#include <cuda_fp16.h>
#include <cstdint>

// LSTM: B=64, T=4096, H=128, gates i,f,g,o; Linear(H->1) on h_T.
// SINGLE-CTA-PER-BATCH mma.sync design (no cluster, no DSMEM, no mbarrier):
// 64 CTAs x 256 threads. W_hh as f16 A-fragments, fully register-resident
// (128 regs/thread across 8 warps; sigmoid-gate rows pre-scaled by 0.5).
// Per step: h (f16x2 in smem, all 8 B-columns replicate h) -> 32x
// mma.sync.m16n8k16.f32.f16.f16.f32 per warp -> 512 gate pre-acts (fp32) to
// smem -> bar -> 128 threads: MUFU.TANH activations, c update, h(f16) store
// -> bar. Two __syncthreads per step, everything else in-SM.

#define B_ 64
#define T_ 4096
#define H_ 128
#define NT 256

__device__ __forceinline__ float tanh_fast(float x) {
    float y; asm("tanh.approx.f32 %0, %1;" : "=f"(y) : "f"(x)); return y;
}
__device__ __forceinline__ uint32_t smem_u32(const void* p) {
    uint32_t a;
    asm("{ .reg .u64 t; cvta.to.shared.u64 t, %1; cvt.u32.u64 %0, t; }" : "=r"(a) : "l"(p));
    return a;
}
__device__ __forceinline__ uint32_t pack2(float a, float b) {
    __half2 h = __floats2half2_rn(a, b);   // a -> low, b -> high
    return *reinterpret_cast<uint32_t*>(&h);
}

__global__ void __launch_bounds__(NT, 1)
lstm_kernel(const float* __restrict__ data, const float* __restrict__ h0,
            const float* __restrict__ c0,   const float* __restrict__ W_ih,
            const float* __restrict__ W_hh, const float* __restrict__ b_ih,
            const float* __restrict__ b_hh, const float* __restrict__ W_out,
            const float* __restrict__ b_out, float* __restrict__ out)
{
    __shared__ __align__(16) uint32_t h2s[H_ / 2];   // h as packed f16x2 (64 words)
    __shared__ __align__(16) float gates_s[4 * H_];  // 512 gate pre-activations
    __shared__ __align__(16) float xs[T_];           // input sequence
    __shared__ __align__(16) float hf[H_];           // final h (fp32) for projection

    const int tid   = threadIdx.x;
    const int batch = blockIdx.x;
    const int w  = tid >> 5;          // warp 0..7 -> gate rows [64w, 64w+64)
    const int l  = tid & 31;
    const int g  = l >> 2;            // groupID 0..7
    const int tg = l & 3;             // threadID-in-group 0..3

    // ---- W_hh -> register-resident A fragments (f16), sigmoid rows pre-scaled ----
    // mma.m16n8k16 A (row-major) fragment: a0=A[g][2tg,2tg+1], a1=A[g+8][...],
    // a2=A[g][2tg+8,+9], a3=A[g+8][2tg+8,+9]; row block rb=64w+16j, kstep k -> col base 16k.
    uint32_t wA[4][8][4];
    #pragma unroll
    for (int j = 0; j < 4; j++) {
        const int rb = 64 * w + 16 * j;
        const int r0 = rb + g, r1 = rb + g + 8;
        const float sc = ((r0 >> 7) == 2) ? 1.f : 0.5f;   // r1 is in the same gate block
        const float* p0 = W_hh + (size_t)r0 * H_;
        const float* p1 = W_hh + (size_t)r1 * H_;
        #pragma unroll
        for (int k = 0; k < 8; k++) {
            const int cb = 16 * k + 2 * tg;
            wA[j][k][0] = pack2(sc * p0[cb],     sc * p0[cb + 1]);
            wA[j][k][1] = pack2(sc * p1[cb],     sc * p1[cb + 1]);
            wA[j][k][2] = pack2(sc * p0[cb + 8], sc * p0[cb + 9]);
            wA[j][k][3] = pack2(sc * p1[cb + 8], sc * p1[cb + 9]);
        }
    }

    // ---- per-thread gate-phase constants (threads 0..127 handle unit u=tid) ----
    float wi0 = 0.f, wi1 = 0.f, wi2 = 0.f, wi3 = 0.f;
    float bi0 = 0.f, bi1 = 0.f, bi2 = 0.f, bi3 = 0.f;
    float c = 0.f;
    if (tid < H_) {
        wi0 = 0.5f * W_ih[tid];            bi0 = 0.5f * (b_ih[tid]            + b_hh[tid]);
        wi1 = 0.5f * W_ih[H_ + tid];       bi1 = 0.5f * (b_ih[H_ + tid]       + b_hh[H_ + tid]);
        wi2 =        W_ih[2 * H_ + tid];   bi2 =        (b_ih[2 * H_ + tid]   + b_hh[2 * H_ + tid]);
        wi3 = 0.5f * W_ih[3 * H_ + tid];   bi3 = 0.5f * (b_ih[3 * H_ + tid]   + b_hh[3 * H_ + tid]);
        c = c0[batch * H_ + tid];
    }

    // ---- h0 (f16x2) + x preload ----
    if (tid < H_ / 2)
        h2s[tid] = pack2(h0[batch * H_ + 2 * tid], h0[batch * H_ + 2 * tid + 1]);
    for (int i = tid; i < T_; i += NT)
        xs[i] = data[(size_t)batch * T_ + i];
    __syncthreads();

    const uint32_t h2_base = smem_u32(&h2s[0]);
    float hn = 0.f;

    #pragma unroll 1
    for (int t = 0; t < T_; ++t) {
        // ---------- phase M: gates = W @ h via mma.sync ----------
        // B (col-major) fragment, all N columns replicate h:
        // b0 = h2s[8k+tg], b1 = h2s[8k+4+tg]  (independent of g)
        uint32_t b0[8], b1[8];
        #pragma unroll
        for (int k = 0; k < 8; k++) {
            b0[k] = h2s[8 * k + tg];
            b1[k] = h2s[8 * k + 4 + tg];
        }
        float d0[4], d1[4], d2[4], d3[4];
        #pragma unroll
        for (int j = 0; j < 4; j++) { d0[j] = d1[j] = d2[j] = d3[j] = 0.f; }
        #pragma unroll
        for (int j = 0; j < 4; j++) {
            #pragma unroll
            for (int k = 0; k < 8; k++) {
                asm("mma.sync.aligned.m16n8k16.row.col.f32.f16.f16.f32 "
                    "{%0,%1,%2,%3}, {%4,%5,%6,%7}, {%8,%9}, {%0,%1,%2,%3};"
                    : "+f"(d0[j]), "+f"(d1[j]), "+f"(d2[j]), "+f"(d3[j])
                    : "r"(wA[j][k][0]), "r"(wA[j][k][1]),
                      "r"(wA[j][k][2]), "r"(wA[j][k][3]),
                      "r"(b0[k]), "r"(b1[k]));
            }
        }
        // D[g][2tg] (=d0) and D[g+8][2tg] (=d2): all columns equal, tg0 lanes store
        if (tg == 0) {
            #pragma unroll
            for (int j = 0; j < 4; j++) {
                gates_s[64 * w + 16 * j + g]     = d0[j];
                gates_s[64 * w + 16 * j + 8 + g] = d2[j];
            }
        }
        __syncthreads();

        // ---------- phase G: activations + state update (threads 0..127) ----------
        if (tid < H_) {
            const float x = xs[t];
            const float pi = gates_s[tid]           + fmaf(wi0, x, bi0);
            const float pf = gates_s[H_ + tid]      + fmaf(wi1, x, bi1);
            const float pg = gates_s[2 * H_ + tid]  + fmaf(wi2, x, bi2);
            const float po = gates_s[3 * H_ + tid]  + fmaf(wi3, x, bi3);

            const float gi = fmaf(tanh_fast(pi), 0.5f, 0.5f);   // sigmoid (pre-scaled)
            const float gf = fmaf(tanh_fast(pf), 0.5f, 0.5f);
            const float gg = tanh_fast(pg);
            const float go = fmaf(tanh_fast(po), 0.5f, 0.5f);

            c  = fmaf(gf, c, gi * gg);
            hn = go * tanh_fast(c);

            const unsigned short hb = __half_as_ushort(__float2half(hn));
            asm volatile("st.shared.b16 [%0], %1;"
                         :: "r"(h2_base + 2u * (uint32_t)tid), "h"(hb) : "memory");
        }
        __syncthreads();   // h2s = h_{t+1} visible; also WAR fence for gates_s
    }

    // ---- final projection: out[batch] = W_out . h_T + b_out ----
    if (tid < H_) hf[tid] = hn;
    __syncthreads();
    if (tid < 32) {
        float s = 0.f;
        #pragma unroll
        for (int m = 0; m < 4; m++)
            s = fmaf(hf[tid * 4 + m], W_out[tid * 4 + m], s);
        #pragma unroll
        for (int off = 16; off; off >>= 1)
            s += __shfl_xor_sync(0xffffffffu, s, off);
        if (tid == 0) out[batch] = s + b_out[0];
    }
}

extern "C" void kernel_launch(void* const* d_in, const int* in_sizes, int n_in,
                              void* d_out, int out_size)
{
    const float* data  = (const float*)d_in[0];
    const float* h0    = (const float*)d_in[1];
    const float* c0    = (const float*)d_in[2];
    const float* W_ih  = (const float*)d_in[3];
    const float* W_hh  = (const float*)d_in[4];
    const float* b_ih  = (const float*)d_in[5];
    const float* b_hh  = (const float*)d_in[6];
    const float* W_out = (const float*)d_in[7];
    const float* b_out = (const float*)d_in[8];
    float* out = (float*)d_out;

    lstm_kernel<<<B_, NT>>>(data, h0, c0, W_ih, W_hh, b_ih, b_hh, W_out, b_out, out);
}

// round 17
// speedup vs baseline: 1.6466x; 1.0057x over previous
#include <cuda_runtime.h>
#include <cuda_fp16.h>
#include <cstdint>

// LSTM: B=64, T=4096, H=128, gates i,f,g,o; Linear(H->1) on h_T.
// SINGLE-CTA-PER-BATCH mma.sync design v2: 64 CTAs x 256 threads.
// Row remap: warp w, m16-tile j = gate j of hidden units [16w, 16w+16).
// After the 32 HMMAs each lane holds ALL 4 gates of its unit in D registers
// (N-columns replicate h), so activations run in-register on all 256 threads:
// tg<2 lanes own unit 16w+g (d0), tg>=2 own 16w+8+g (d2). No gates smem.
// B-fragments built from 2 LDS + 16 shfl.idx (h cached 1 word/lane).
// h double-buffered in smem (f16x2) -> ONE __syncthreads per step.

#define B_ 64
#define T_ 4096
#define H_ 128
#define NT 256

__device__ __forceinline__ float tanh_fast(float x) {
    float y; asm("tanh.approx.f32 %0, %1;" : "=f"(y) : "f"(x)); return y;
}
__device__ __forceinline__ uint32_t smem_u32(const void* p) {
    uint32_t a;
    asm("{ .reg .u64 t; cvta.to.shared.u64 t, %1; cvt.u32.u64 %0, t; }" : "=r"(a) : "l"(p));
    return a;
}
__device__ __forceinline__ uint32_t pack2(float a, float b) {
    __half2 h = __floats2half2_rn(a, b);   // a -> low, b -> high
    return *reinterpret_cast<uint32_t*>(&h);
}

__global__ void __launch_bounds__(NT, 1)
lstm_kernel(const float* __restrict__ data, const float* __restrict__ h0,
            const float* __restrict__ c0,   const float* __restrict__ W_ih,
            const float* __restrict__ W_hh, const float* __restrict__ b_ih,
            const float* __restrict__ b_hh, const float* __restrict__ W_out,
            const float* __restrict__ b_out, float* __restrict__ out)
{
    __shared__ __align__(16) uint32_t h2s[2][H_ / 2];  // double-buffered h (f16x2)
    __shared__ __align__(16) float xs[T_];             // input sequence
    __shared__ __align__(16) float hf[H_];             // final h (fp32)

    const int tid   = threadIdx.x;
    const int batch = blockIdx.x;
    const int w  = tid >> 5;          // warp 0..7 -> units [16w, 16w+16)
    const int l  = tid & 31;
    const int g  = l >> 2;            // groupID 0..7
    const int tg = l & 3;             // threadID-in-group 0..3
    const int myu = 16 * w + ((tg < 2) ? g : 8 + g);   // this lane's hidden unit

    // ---- W_hh -> register-resident A fragments (f16) ----
    // tile j (gate j) of warp w: rows j*128 + 16w + (0..15).
    // a0: row g cols 2tg,2tg+1 ; a1: row g+8 ; a2/a3: cols +8. Sigmoid gates x0.5.
    uint32_t wA[4][8][4];
    #pragma unroll
    for (int j = 0; j < 4; j++) {
        const int r0row = j * H_ + 16 * w + g;
        const int r1row = r0row + 8;
        const float sc = (j == 2) ? 1.f : 0.5f;
        const float* p0 = W_hh + (size_t)r0row * H_;
        const float* p1 = W_hh + (size_t)r1row * H_;
        #pragma unroll
        for (int k = 0; k < 8; k++) {
            const int cb = 16 * k + 2 * tg;
            wA[j][k][0] = pack2(sc * p0[cb],     sc * p0[cb + 1]);
            wA[j][k][1] = pack2(sc * p1[cb],     sc * p1[cb + 1]);
            wA[j][k][2] = pack2(sc * p0[cb + 8], sc * p0[cb + 9]);
            wA[j][k][3] = pack2(sc * p1[cb + 8], sc * p1[cb + 9]);
        }
    }

    // per-unit input-weight / bias constants (pre-scaled), and cell state
    float wi[4], bi[4];
    #pragma unroll
    for (int j = 0; j < 4; j++) {
        const int jr = j * H_ + myu;
        const float sc = (j == 2) ? 1.f : 0.5f;
        wi[j] = sc * W_ih[jr];
        bi[j] = sc * (b_ih[jr] + b_hh[jr]);
    }
    float c = c0[batch * H_ + myu];

    // h0 (f16x2 into buffer 0) + x preload
    if (tid < H_ / 2)
        h2s[0][tid] = pack2(h0[batch * H_ + 2 * tid], h0[batch * H_ + 2 * tid + 1]);
    for (int i = tid; i < T_; i += NT)
        xs[i] = data[(size_t)batch * T_ + i];
    __syncthreads();

    const uint32_t hbase = smem_u32(&h2s[0][0]);
    const uint32_t hst   = hbase + 2u * (uint32_t)myu;   // + 256*(p^1) per step
    float hn = 0.f;

    #pragma unroll 1
    for (int t = 0; t < T_; ++t) {
        const int p = t & 1;

        // ---- h words cached 1/lane, B-fragments via shfl ----
        const uint32_t r0 = h2s[p][l];
        const uint32_t r1 = h2s[p][32 + l];
        const float x = xs[t];
        float bx[4];
        #pragma unroll
        for (int j = 0; j < 4; j++) bx[j] = fmaf(wi[j], x, bi[j]);

        uint32_t b0[8], b1[8];
        #pragma unroll
        for (int k = 0; k < 4; k++) {
            b0[k]     = __shfl_sync(0xffffffffu, r0, 8 * k + tg);
            b1[k]     = __shfl_sync(0xffffffffu, r0, 8 * k + 4 + tg);
            b0[4 + k] = __shfl_sync(0xffffffffu, r1, 8 * k + tg);
            b1[4 + k] = __shfl_sync(0xffffffffu, r1, 8 * k + 4 + tg);
        }

        // ---- 32 HMMAs: D[j] = gate j of units [16w,16w+16) ----
        float d0[4], d1[4], d2[4], d3[4];
        #pragma unroll
        for (int j = 0; j < 4; j++) { d0[j] = d1[j] = d2[j] = d3[j] = 0.f; }
        #pragma unroll
        for (int j = 0; j < 4; j++) {
            #pragma unroll
            for (int k = 0; k < 8; k++) {
                asm("mma.sync.aligned.m16n8k16.row.col.f32.f16.f16.f32 "
                    "{%0,%1,%2,%3}, {%4,%5,%6,%7}, {%8,%9}, {%0,%1,%2,%3};"
                    : "+f"(d0[j]), "+f"(d1[j]), "+f"(d2[j]), "+f"(d3[j])
                    : "r"(wA[j][k][0]), "r"(wA[j][k][1]),
                      "r"(wA[j][k][2]), "r"(wA[j][k][3]),
                      "r"(b0[k]), "r"(b1[k]));
            }
        }

        // ---- in-register activations: this lane's unit = myu ----
        float pre[4];
        #pragma unroll
        for (int j = 0; j < 4; j++)
            pre[j] = ((tg < 2) ? d0[j] : d2[j]) + bx[j];

        const float gi = fmaf(tanh_fast(pre[0]), 0.5f, 0.5f);   // sigmoid (pre-scaled)
        const float gf = fmaf(tanh_fast(pre[1]), 0.5f, 0.5f);
        const float gg = tanh_fast(pre[2]);
        const float go = fmaf(tanh_fast(pre[3]), 0.5f, 0.5f);

        c  = fmaf(gf, c, gi * gg);
        hn = go * tanh_fast(c);

        // store h (f16) to the other buffer; lanes tg==0 / tg==2 own distinct units
        if ((tg & 1) == 0) {
            const unsigned short hb = __half_as_ushort(__float2half(hn));
            asm volatile("st.shared.b16 [%0], %1;"
                         :: "r"(hst + 256u * (uint32_t)(p ^ 1)), "h"(hb) : "memory");
        }
        __syncthreads();   // h_{t+1} visible for next step's loads
    }

    // ---- final projection: out[batch] = W_out . h_T + b_out ----
    if ((tg & 1) == 0) hf[myu] = hn;
    __syncthreads();
    if (tid < 32) {
        float s = 0.f;
        #pragma unroll
        for (int m = 0; m < 4; m++)
            s = fmaf(hf[tid * 4 + m], W_out[tid * 4 + m], s);
        #pragma unroll
        for (int off = 16; off; off >>= 1)
            s += __shfl_xor_sync(0xffffffffu, s, off);
        if (tid == 0) out[batch] = s + b_out[0];
    }
}

extern "C" void kernel_launch(void* const* d_in, const int* in_sizes, int n_in,
                              void* d_out, int out_size)
{
    const float* data  = (const float*)d_in[0];
    const float* h0    = (const float*)d_in[1];
    const float* c0    = (const float*)d_in[2];
    const float* W_ih  = (const float*)d_in[3];
    const float* W_hh  = (const float*)d_in[4];
    const float* b_ih  = (const float*)d_in[5];
    const float* b_hh  = (const float*)d_in[6];
    const float* W_out = (const float*)d_in[7];
    const float* b_out = (const float*)d_in[8];
    float* out = (float*)d_out;

    lstm_kernel<<<B_, NT>>>(data, h0, c0, W_ih, W_hh, b_ih, b_hh, W_out, b_out, out);
}